// round 13
// baseline (speedup 1.0000x reference)
#include <cuda_runtime.h>
#include <cuda_bf16.h>
#include <math.h>
#include <stdint.h>

#define B_SZ   16384
#define NTAB   26
#define VOCAB  100000
#define EMB_D  64

// ======================= scratch (device globals) ==========================
__device__ __align__(256) float g_x [B_SZ * 64];            // bot MLP out fp32
__device__ __align__(256) float g_z2[B_SZ * 256];           // top L1 out fp32

__device__ __align__(256) __nv_bfloat16 g_x1h[B_SZ * 512];
__device__ __align__(256) __nv_bfloat16 g_x1l[B_SZ * 512];
__device__ __align__(256) __nv_bfloat16 g_x2h[B_SZ * 256];
__device__ __align__(256) __nv_bfloat16 g_x2l[B_SZ * 256];
__device__ __align__(256) __nv_bfloat16 g_Rh [B_SZ * 448];
__device__ __align__(256) __nv_bfloat16 g_Rl [B_SZ * 448];
__device__ __align__(256) __nv_bfloat16 g_z1h[B_SZ * 512];
__device__ __align__(256) __nv_bfloat16 g_z1l[B_SZ * 512];

__device__ __align__(256) __nv_bfloat16 g_bW1h[256 * 512];
__device__ __align__(256) __nv_bfloat16 g_bW1l[256 * 512];
__device__ __align__(256) __nv_bfloat16 g_bW2h[64 * 256];
__device__ __align__(256) __nv_bfloat16 g_bW2l[64 * 256];
__device__ __align__(256) __nv_bfloat16 g_tW0h[512 * 448];
__device__ __align__(256) __nv_bfloat16 g_tW0l[512 * 448];
__device__ __align__(256) __nv_bfloat16 g_tW1h[256 * 512];
__device__ __align__(256) __nv_bfloat16 g_tW1l[256 * 512];

__device__ int g_idx_is64;

// ======================= helpers ============================================
__device__ __forceinline__ uint32_t smem_u32(const void* p) {
    uint32_t a;
    asm("{ .reg .u64 t; cvta.to.shared.u64 t, %1; cvt.u32.u64 %0, t; }"
        : "=r"(a) : "l"(p));
    return a;
}
__device__ __forceinline__ void cpa16(uint32_t saddr, const void* g) {
    asm volatile("cp.async.cg.shared.global [%0], [%1], 16;" :: "r"(saddr), "l"(g));
}
__device__ __forceinline__ void cpa_commit() {
    asm volatile("cp.async.commit_group;" ::: "memory");
}
__device__ __forceinline__ void cpa_wait1() {
    asm volatile("cp.async.wait_group 1;" ::: "memory");
}
__device__ __forceinline__ void cpa_wait0() {
    asm volatile("cp.async.wait_group 0;" ::: "memory");
}
__device__ __forceinline__ void ldm_x4(uint32_t a, uint32_t& r0, uint32_t& r1,
                                       uint32_t& r2, uint32_t& r3) {
    asm volatile("ldmatrix.sync.aligned.m8n8.x4.shared.b16 {%0,%1,%2,%3}, [%4];"
                 : "=r"(r0), "=r"(r1), "=r"(r2), "=r"(r3) : "r"(a));
}
__device__ __forceinline__ void mma16816(float* c, const uint32_t* a,
                                         const uint32_t* b) {
    asm volatile(
        "mma.sync.aligned.m16n8k16.row.col.f32.bf16.bf16.f32 "
        "{%0,%1,%2,%3}, {%4,%5,%6,%7}, {%8,%9}, {%0,%1,%2,%3};"
        : "+f"(c[0]), "+f"(c[1]), "+f"(c[2]), "+f"(c[3])
        : "r"(a[0]), "r"(a[1]), "r"(a[2]), "r"(a[3]), "r"(b[0]), "r"(b[1]));
}
__device__ __forceinline__ void split_f32(float v, __nv_bfloat16& h, __nv_bfloat16& l) {
    h = __float2bfloat16(v);
    l = __float2bfloat16(v - __bfloat162float(h));
}

// ===== launch 0: fused prep (pad/split weights + idx detect) + bot layer 0 ==
__device__ __forceinline__ void padsplit_one(const float* W, __nv_bfloat16* Wh,
                                             __nv_bfloat16* Wl, int i,
                                             int Kin, int Kpad) {
    const int n = i / Kpad;
    const int k = i - n * Kpad;
    const float v = (k < Kin) ? W[n * Kin + k] : 0.f;
    __nv_bfloat16 h, l; split_f32(v, h, l);
    Wh[i] = h; Wl[i] = l;
}

__global__ void __launch_bounds__(256) prep_bot0_kernel(
    const float* __restrict__ X, const float* __restrict__ bW0,
    const float* __restrict__ bb0,
    __nv_bfloat16* __restrict__ Yh, __nv_bfloat16* __restrict__ Yl,
    const float* __restrict__ bW1, const float* __restrict__ bW2,
    const float* __restrict__ tW0, const float* __restrict__ tW1,
    const int* __restrict__ lsi32,
    __nv_bfloat16* __restrict__ bW1h, __nv_bfloat16* __restrict__ bW1l,
    __nv_bfloat16* __restrict__ bW2h, __nv_bfloat16* __restrict__ bW2l,
    __nv_bfloat16* __restrict__ tW0h, __nv_bfloat16* __restrict__ tW0l,
    __nv_bfloat16* __restrict__ tW1h, __nv_bfloat16* __restrict__ tW1l)
{
    const int bid = blockIdx.x;
    const int tid = threadIdx.x;
    if (bid < 1024) {
        __shared__ float sW[512 * 13];
        __shared__ float sb[512];
        __shared__ float sx[16 * 13];
        const int r0 = bid * 16;
        for (int i = tid; i < 512 * 13; i += 256) sW[i] = bW0[i];
        for (int i = tid; i < 512; i += 256) sb[i] = bb0[i];
        for (int i = tid; i < 16 * 13; i += 256) sx[i] = X[r0 * 13 + i];
        __syncthreads();
        for (int o = tid; o < 16 * 512; o += 256) {
            const int r = o >> 9;
            const int c = o & 511;
            float acc = sb[c];
            #pragma unroll
            for (int k = 0; k < 13; k++) acc += sx[r * 13 + k] * sW[c * 13 + k];
            acc = fmaxf(acc, 0.f);
            __nv_bfloat16 h, l; split_f32(acc, h, l);
            const size_t idx = (size_t)(r0 + r) * 512 + c;
            Yh[idx] = h; Yl[idx] = l;
        }
        return;
    }
    if (bid == 3008) {
        if (tid < 32) {
            int any = 0;
            for (int k = tid; k < 2048; k += 32)
                if (lsi32[2 * k + 1] != 0) any = 1;
            any = __any_sync(0xFFFFFFFFu, any);
            if (tid == 0) g_idx_is64 = any ? 0 : 1;
        }
        return;
    }
    const int i = (bid - 1024) * 256 + tid;
    if (i < 131072) {
        padsplit_one(bW1, bW1h, bW1l, i, 512, 512);
    } else if (i < 147456) {
        padsplit_one(bW2, bW2h, bW2l, i - 131072, 256, 256);
    } else if (i < 376832) {
        padsplit_one(tW0, tW0h, tW0l, i - 147456, 415, 448);
    } else {
        padsplit_one(tW1, tW1h, tW1l, i - 376832, 512, 512);
    }
}

// ======================= mma.sync bf16x3 GEMM (NT=64, 2 CTA/SM) =============
#define STG 49152u
__device__ __forceinline__ uint32_t swz(int row, int chunk) {
    return (uint32_t)(row * 128 + ((chunk ^ (row & 7)) * 16));
}

__global__ void __launch_bounds__(256) gemm_mma(
    const __nv_bfloat16* __restrict__ Ah, const __nv_bfloat16* __restrict__ Al,
    const __nv_bfloat16* __restrict__ Wh, const __nv_bfloat16* __restrict__ Wl,
    const float* __restrict__ bias, int K, int NC,
    float* __restrict__ Cf,
    __nv_bfloat16* __restrict__ Ch, __nv_bfloat16* __restrict__ Cl,
    int ldc, int relu, int splitOut)
{
    extern __shared__ char smem[];
    const uint32_t sb = smem_u32(smem);
    const int tid  = threadIdx.x;
    const int lane = tid & 31;
    const int wid  = tid >> 5;
    const int wm   = wid >> 1;
    const int wn   = wid & 1;
    const int m0 = blockIdx.y * 128;
    const int n0 = blockIdx.x * 64;
    const size_t rowB = (size_t)K * 2;

    const char* gAh = (const char*)Ah + (size_t)m0 * rowB;
    const char* gAl = (const char*)Al + (size_t)m0 * rowB;
    const char* gWh = (const char*)Wh + (size_t)n0 * rowB;
    const char* gWl = (const char*)Wl + (size_t)n0 * rowB;

    float acc[2][4][4];
    #pragma unroll
    for (int t = 0; t < 2; t++)
        #pragma unroll
        for (int u = 0; u < 4; u++)
            #pragma unroll
            for (int v = 0; v < 4; v++) acc[t][u][v] = 0.f;

    auto load_stage = [&](int c) {
        const uint32_t so = sb + (uint32_t)(c & 1) * STG;
        const size_t kb = (size_t)c * 128;
        #pragma unroll
        for (int i = 0; i < 4; i++) {
            const int e = tid + i * 256;
            const int row = e >> 3;
            const int ch  = e & 7;
            const size_t gs = (size_t)row * rowB + kb + ch * 16;
            const uint32_t d = swz(row, ch);
            cpa16(so + d,          gAh + gs);
            cpa16(so + 16384 + d,  gAl + gs);
        }
        #pragma unroll
        for (int i = 0; i < 2; i++) {
            const int e = tid + i * 256;
            const int row = e >> 3;
            const int ch  = e & 7;
            const size_t gs = (size_t)row * rowB + kb + ch * 16;
            const uint32_t d = swz(row, ch);
            cpa16(so + 32768 + d, gWh + gs);
            cpa16(so + 40960 + d, gWl + gs);
        }
        cpa_commit();
    };

    load_stage(0);
    for (int c = 0; c < NC; ++c) {
        if (c + 1 < NC) load_stage(c + 1);
        if (c + 1 < NC) cpa_wait1(); else cpa_wait0();
        __syncthreads();

        const uint32_t so = sb + (uint32_t)(c & 1) * STG;
        const uint32_t sAhB = so, sAlB = so + 16384;
        const uint32_t sWhB = so + 32768, sWlB = so + 40960;

        #pragma unroll
        for (int kk = 0; kk < 4; kk++) {
            uint32_t ah[2][4], al[2][4], bh[8], bl[8];
            #pragma unroll
            for (int t = 0; t < 2; t++) {
                const int row = wm * 32 + t * 16 + (lane & 15);
                const int ch  = kk * 2 + (lane >> 4);
                const uint32_t d = swz(row, ch);
                ldm_x4(sAhB + d, ah[t][0], ah[t][1], ah[t][2], ah[t][3]);
                ldm_x4(sAlB + d, al[t][0], al[t][1], al[t][2], al[t][3]);
            }
            #pragma unroll
            for (int p = 0; p < 2; p++) {
                const int row = wn * 32 + p * 16 + ((lane >> 4) & 1) * 8 + (lane & 7);
                const int ch  = kk * 2 + ((lane >> 3) & 1);
                const uint32_t d = swz(row, ch);
                ldm_x4(sWhB + d, bh[p * 4 + 0], bh[p * 4 + 1], bh[p * 4 + 2], bh[p * 4 + 3]);
                ldm_x4(sWlB + d, bl[p * 4 + 0], bl[p * 4 + 1], bl[p * 4 + 2], bl[p * 4 + 3]);
            }
            #pragma unroll
            for (int t = 0; t < 2; t++)
                #pragma unroll
                for (int u = 0; u < 4; u++) {
                    mma16816(acc[t][u], ah[t], &bh[u * 2]);
                    mma16816(acc[t][u], ah[t], &bl[u * 2]);
                    mma16816(acc[t][u], al[t], &bh[u * 2]);
                }
        }
        __syncthreads();
    }

    #pragma unroll
    for (int t = 0; t < 2; t++) {
        const int rbase = m0 + wm * 32 + t * 16 + (lane >> 2);
        #pragma unroll
        for (int u = 0; u < 4; u++) {
            const int gn = n0 + wn * 32 + u * 8 + (lane & 3) * 2;
            const float b0 = __ldg(&bias[gn]);
            const float b1 = __ldg(&bias[gn + 1]);
            #pragma unroll
            for (int h = 0; h < 2; h++) {
                float v0 = acc[t][u][h * 2 + 0] + b0;
                float v1 = acc[t][u][h * 2 + 1] + b1;
                if (relu) { v0 = fmaxf(v0, 0.f); v1 = fmaxf(v1, 0.f); }
                const size_t idx = (size_t)(rbase + h * 8) * ldc + gn;
                if (splitOut) {
                    __nv_bfloat16 h0, l0, h1, l1;
                    split_f32(v0, h0, l0); split_f32(v1, h1, l1);
                    *reinterpret_cast<__nv_bfloat162*>(Ch + idx) = __halves2bfloat162(h0, h1);
                    *reinterpret_cast<__nv_bfloat162*>(Cl + idx) = __halves2bfloat162(l0, l1);
                } else {
                    *reinterpret_cast<float2*>(Cf + idx) = make_float2(v0, v1);
                }
            }
        }
    }
}

// ======== fused gather + tensor-core interaction (4-warp MMA) ===============
// Gather writes T (32x64, rows 27-31 zero) to smem as split bf16 (hi/lo),
// XOR-swizzled 128B rows. All 4 warps compute Z = T*T^T: warp w owns
// m-tile (w>>1) x n-half (w&1) of the 32x32 output, bf16x3 m16n8k16 mma.
__global__ void __launch_bounds__(128, 12) gather_interact_kernel(
    const float* __restrict__ x, const float* __restrict__ emb,
    const void* __restrict__ lsi,
    __nv_bfloat16* __restrict__ Rh, __nv_bfloat16* __restrict__ Rl)
{
    __shared__ __nv_bfloat16 sTh[32 * 64];   // 32 rows x 128B (swizzled)
    __shared__ __nv_bfloat16 sTl[32 * 64];
    const int b   = blockIdx.x;
    const int tid = threadIdx.x;
    const int hw  = tid >> 4;       // half-warp 0..7
    const int lh  = tid & 15;       // lane in half-warp
    const int is64 = g_idx_is64;
    const long long* ip64 = (const long long*)lsi;
    const int*       ip32 = (const int*)lsi;
    const uint32_t th = smem_u32(sTh);
    const uint32_t tl = smem_u32(sTl);

    // zero pad rows 27..31 (5 rows x 128B each array)
    for (int i = tid; i < 40; i += 128) {
        reinterpret_cast<uint4*>(sTh)[27 * 8 + i] = make_uint4(0, 0, 0, 0);
        reinterpret_cast<uint4*>(sTl)[27 * 8 + i] = make_uint4(0, 0, 0, 0);
    }

    // x row -> row 0 (row 0 swizzle is identity)
    if (tid < 16) {
        float4 v = *reinterpret_cast<const float4*>(x + (size_t)b * 64 + lh * 4);
        __nv_bfloat16 h0, l0, h1, l1, h2, l2, h3, l3;
        split_f32(v.x, h0, l0); split_f32(v.y, h1, l1);
        split_f32(v.z, h2, l2); split_f32(v.w, h3, l3);
        *reinterpret_cast<__nv_bfloat162*>(&sTh[lh * 4])     = __halves2bfloat162(h0, h1);
        *reinterpret_cast<__nv_bfloat162*>(&sTh[lh * 4 + 2]) = __halves2bfloat162(h2, h3);
        *reinterpret_cast<__nv_bfloat162*>(&sTl[lh * 4])     = __halves2bfloat162(l0, l1);
        *reinterpret_cast<__nv_bfloat162*>(&sTl[lh * 4 + 2]) = __halves2bfloat162(l2, l3);
    }

    // embedding gather-sum: half-warp hw owns tables hw, hw+8, hw+16, hw+24
    #pragma unroll
    for (int r = 0; r < 4; r++) {
        const int t = hw + r * 8;
        if (t >= NTAB) break;
        const size_t ibase = ((size_t)t * B_SZ + b) * 4;
        const float* tb = emb + (size_t)t * (VOCAB * EMB_D);
        float4 acc = make_float4(0.f, 0.f, 0.f, 0.f);
        #pragma unroll
        for (int l = 0; l < 4; l++) {
            unsigned int ix = is64 ? (unsigned int)ip64[ibase + l]
                                   : (unsigned int)ip32[ibase + l];
            if (ix >= VOCAB) ix = VOCAB - 1;
            const float4* row = reinterpret_cast<const float4*>(tb + (size_t)ix * EMB_D);
            float4 v = __ldg(row + lh);
            acc.x += v.x; acc.y += v.y; acc.z += v.z; acc.w += v.w;
        }
        __nv_bfloat16 h0, l0, h1, l1, h2, l2, h3, l3;
        split_f32(acc.x, h0, l0); split_f32(acc.y, h1, l1);
        split_f32(acc.z, h2, l2); split_f32(acc.w, h3, l3);
        const int row = 1 + t;
        const uint32_t off = swz(row, lh >> 1) + (lh & 1) * 8;  // byte offset
        *reinterpret_cast<__nv_bfloat162*>((char*)sTh + off)     = __halves2bfloat162(h0, h1);
        *reinterpret_cast<__nv_bfloat162*>((char*)sTh + off + 4) = __halves2bfloat162(h2, h3);
        *reinterpret_cast<__nv_bfloat162*>((char*)sTl + off)     = __halves2bfloat162(l0, l1);
        *reinterpret_cast<__nv_bfloat162*>((char*)sTl + off + 4) = __halves2bfloat162(l2, l3);
    }
    __syncthreads();

    __nv_bfloat16* Rbh = Rh + (size_t)b * 448;
    __nv_bfloat16* Rbl = Rl + (size_t)b * 448;

    // R[0:64] = x (row 0 is linear in smem); pad tail
    if (tid >= 64 && tid < 128) {
        const int c = tid - 64;
        Rbh[c] = sTh[c]; Rbl[c] = sTl[c];
    }
    for (int c = 415 + tid; c < 448; c += 128) {
        Rbh[c] = __float2bfloat16(0.f); Rbl[c] = __float2bfloat16(0.f);
    }

    // Z = T*T^T via mma: warp w -> m rows [wm2*16,+16) x n cols [wn2*16,+16)
    const int wid  = tid >> 5;
    const int lane = tid & 31;
    const int wm2  = wid >> 1;
    const int wn2  = wid & 1;
    {
        float acc[2][4];
        #pragma unroll
        for (int u = 0; u < 2; u++)
            #pragma unroll
            for (int v = 0; v < 4; v++) acc[u][v] = 0.f;

        #pragma unroll
        for (int kk = 0; kk < 4; kk++) {
            uint32_t ah[4], al[4], bh[4], bl[4];
            {
                const int row = wm2 * 16 + (lane & 15);
                const int ch  = kk * 2 + (lane >> 4);
                const uint32_t d = swz(row, ch);
                ldm_x4(th + d, ah[0], ah[1], ah[2], ah[3]);
                ldm_x4(tl + d, al[0], al[1], al[2], al[3]);
            }
            {
                const int row = wn2 * 16 + ((lane >> 4) & 1) * 8 + (lane & 7);
                const int ch  = kk * 2 + ((lane >> 3) & 1);
                const uint32_t d = swz(row, ch);
                ldm_x4(th + d, bh[0], bh[1], bh[2], bh[3]);
                ldm_x4(tl + d, bl[0], bl[1], bl[2], bl[3]);
            }
            #pragma unroll
            for (int u = 0; u < 2; u++) {
                mma16816(acc[u], ah, &bh[u * 2]);
                mma16816(acc[u], ah, &bl[u * 2]);
                mma16816(acc[u], al, &bh[u * 2]);
            }
        }

        // scatter lower triangle
        const int ib = wm2 * 16 + (lane >> 2);
        #pragma unroll
        for (int u = 0; u < 2; u++) {
            const int jn = wn2 * 16 + u * 8 + (lane & 3) * 2;
            #pragma unroll
            for (int h = 0; h < 2; h++) {
                const int i = ib + h * 8;
                #pragma unroll
                for (int e = 0; e < 2; e++) {
                    const int j = jn + e;
                    if (i > j && i < 27 && j < 27) {
                        __nv_bfloat16 hh, ll;
                        split_f32(acc[u][h * 2 + e], hh, ll);
                        const int p = i * (i - 1) / 2 + j;
                        Rbh[64 + p] = hh; Rbl[64 + p] = ll;
                    }
                }
            }
        }
    }
}

// ======================= final layer + sigmoid ==============================
__global__ void __launch_bounds__(256) top_final_kernel(
    const float* __restrict__ Z, const float* __restrict__ W,
    const float* __restrict__ bias, float* __restrict__ out)
{
    const int b = blockIdx.x * 8 + (threadIdx.x >> 5);
    const int lane = threadIdx.x & 31;
    const float* zr = Z + (size_t)b * 256;
    float acc = 0.f;
    #pragma unroll
    for (int k = lane; k < 256; k += 32) acc += zr[k] * W[k];
    #pragma unroll
    for (int off = 16; off > 0; off >>= 1)
        acc += __shfl_xor_sync(0xFFFFFFFFu, acc, off);
    if (lane == 0) {
        const float v = acc + bias[0];
        out[b] = 1.f / (1.f + expf(-v));
    }
}

// ======================= launch =============================================
extern "C" void kernel_launch(void* const* d_in, const int* in_sizes, int n_in,
                              void* d_out, int out_size)
{
    (void)n_in; (void)out_size;
    const float* dense_x = (const float*)d_in[0];
    const void*  lsi     = d_in[2];
    const float* emb     = (const float*)d_in[3];

    const float *bW0, *bb0, *bW1, *bb1, *bW2, *bb2;
    const float *tW0, *tb0, *tW1, *tb1, *tW2, *tb2;
    if (in_sizes[6] == 512 * 415) {
        bW0 = (const float*)d_in[4];  bb0 = (const float*)d_in[5];
        tW0 = (const float*)d_in[6];  tb0 = (const float*)d_in[7];
        bW1 = (const float*)d_in[8];  bb1 = (const float*)d_in[9];
        tW1 = (const float*)d_in[10]; tb1 = (const float*)d_in[11];
        bW2 = (const float*)d_in[12]; bb2 = (const float*)d_in[13];
        tW2 = (const float*)d_in[14]; tb2 = (const float*)d_in[15];
    } else {
        bW0 = (const float*)d_in[4];  bb0 = (const float*)d_in[5];
        bW1 = (const float*)d_in[6];  bb1 = (const float*)d_in[7];
        bW2 = (const float*)d_in[8];  bb2 = (const float*)d_in[9];
        tW0 = (const float*)d_in[10]; tb0 = (const float*)d_in[11];
        tW1 = (const float*)d_in[12]; tb1 = (const float*)d_in[13];
        tW2 = (const float*)d_in[14]; tb2 = (const float*)d_in[15];
    }

    float *x, *z2;
    __nv_bfloat16 *x1h, *x1l, *x2h, *x2l, *Rh, *Rl, *z1h, *z1l;
    __nv_bfloat16 *bW1h, *bW1l, *bW2h, *bW2l, *tW0h, *tW0l, *tW1h, *tW1l;
    cudaGetSymbolAddress((void**)&x,    g_x);
    cudaGetSymbolAddress((void**)&z2,   g_z2);
    cudaGetSymbolAddress((void**)&x1h,  g_x1h);  cudaGetSymbolAddress((void**)&x1l, g_x1l);
    cudaGetSymbolAddress((void**)&x2h,  g_x2h);  cudaGetSymbolAddress((void**)&x2l, g_x2l);
    cudaGetSymbolAddress((void**)&Rh,   g_Rh);   cudaGetSymbolAddress((void**)&Rl,  g_Rl);
    cudaGetSymbolAddress((void**)&z1h,  g_z1h);  cudaGetSymbolAddress((void**)&z1l, g_z1l);
    cudaGetSymbolAddress((void**)&bW1h, g_bW1h); cudaGetSymbolAddress((void**)&bW1l, g_bW1l);
    cudaGetSymbolAddress((void**)&bW2h, g_bW2h); cudaGetSymbolAddress((void**)&bW2l, g_bW2l);
    cudaGetSymbolAddress((void**)&tW0h, g_tW0h); cudaGetSymbolAddress((void**)&tW0l, g_tW0l);
    cudaGetSymbolAddress((void**)&tW1h, g_tW1h); cudaGetSymbolAddress((void**)&tW1l, g_tW1l);

    const int SMEM = 2 * 49152;   // 96KB -> 2 CTA/SM
    cudaFuncSetAttribute(gemm_mma, cudaFuncAttributeMaxDynamicSharedMemorySize, SMEM);

    // launch 0: fused prep (pad/split + detect) + bot layer 0
    prep_bot0_kernel<<<3009, 256>>>(dense_x, bW0, bb0, x1h, x1l,
                                    bW1, bW2, tW0, tW1, (const int*)lsi,
                                    bW1h, bW1l, bW2h, bW2l,
                                    tW0h, tW0l, tW1h, tW1l);

    // launches 1-2: rest of bottom MLP -> compact x[B,64]
    gemm_mma<<<dim3(4, 128), 256, SMEM>>>(x1h, x1l, bW1h, bW1l, bb1, 512, 8,
                                          nullptr, x2h, x2l, 256, 1, 1);
    gemm_mma<<<dim3(1, 128), 256, SMEM>>>(x2h, x2l, bW2h, bW2l, bb2, 256, 4,
                                          x, nullptr, nullptr, 64, 1, 0);

    // launch 3: fused gather + tensor-core interaction -> split R[B,448]
    gather_interact_kernel<<<B_SZ, 128>>>(x, emb, lsi, Rh, Rl);

    // launches 4-6: top MLP
    gemm_mma<<<dim3(8, 128), 256, SMEM>>>(Rh, Rl, tW0h, tW0l, tb0, 448, 7,
                                          nullptr, z1h, z1l, 512, 1, 1);
    gemm_mma<<<dim3(4, 128), 256, SMEM>>>(z1h, z1l, tW1h, tW1l, tb1, 512, 8,
                                          z2, nullptr, nullptr, 256, 1, 0);
    top_final_kernel<<<B_SZ / 8, 256>>>(z2, tW2, tb2, (float*)d_out);
}

// round 14
// speedup vs baseline: 1.0285x; 1.0285x over previous
#include <cuda_runtime.h>
#include <cuda_bf16.h>
#include <math.h>
#include <stdint.h>

#define B_SZ   16384
#define NTAB   26
#define VOCAB  100000
#define EMB_D  64

// ======================= scratch (device globals) ==========================
__device__ __align__(256) float g_x  [B_SZ * 64];           // bot MLP out fp32
__device__ __align__(256) float g_dot[B_SZ];                // fused final-dot acc

__device__ __align__(256) __nv_bfloat16 g_x1h[B_SZ * 512];
__device__ __align__(256) __nv_bfloat16 g_x1l[B_SZ * 512];
__device__ __align__(256) __nv_bfloat16 g_x2h[B_SZ * 256];
__device__ __align__(256) __nv_bfloat16 g_x2l[B_SZ * 256];
__device__ __align__(256) __nv_bfloat16 g_Rh [B_SZ * 448];
__device__ __align__(256) __nv_bfloat16 g_Rl [B_SZ * 448];
__device__ __align__(256) __nv_bfloat16 g_z1h[B_SZ * 512];
__device__ __align__(256) __nv_bfloat16 g_z1l[B_SZ * 512];

__device__ __align__(256) __nv_bfloat16 g_bW1h[256 * 512];
__device__ __align__(256) __nv_bfloat16 g_bW1l[256 * 512];
__device__ __align__(256) __nv_bfloat16 g_bW2h[64 * 256];
__device__ __align__(256) __nv_bfloat16 g_bW2l[64 * 256];
__device__ __align__(256) __nv_bfloat16 g_tW0h[512 * 448];
__device__ __align__(256) __nv_bfloat16 g_tW0l[512 * 448];
__device__ __align__(256) __nv_bfloat16 g_tW1h[256 * 512];
__device__ __align__(256) __nv_bfloat16 g_tW1l[256 * 512];

__device__ int g_idx_is64;

// ======================= helpers ============================================
__device__ __forceinline__ uint32_t smem_u32(const void* p) {
    uint32_t a;
    asm("{ .reg .u64 t; cvta.to.shared.u64 t, %1; cvt.u32.u64 %0, t; }"
        : "=r"(a) : "l"(p));
    return a;
}
__device__ __forceinline__ void cpa16(uint32_t saddr, const void* g) {
    asm volatile("cp.async.cg.shared.global [%0], [%1], 16;" :: "r"(saddr), "l"(g));
}
__device__ __forceinline__ void cpa_commit() {
    asm volatile("cp.async.commit_group;" ::: "memory");
}
__device__ __forceinline__ void cpa_wait1() {
    asm volatile("cp.async.wait_group 1;" ::: "memory");
}
__device__ __forceinline__ void cpa_wait0() {
    asm volatile("cp.async.wait_group 0;" ::: "memory");
}
__device__ __forceinline__ void ldm_x4(uint32_t a, uint32_t& r0, uint32_t& r1,
                                       uint32_t& r2, uint32_t& r3) {
    asm volatile("ldmatrix.sync.aligned.m8n8.x4.shared.b16 {%0,%1,%2,%3}, [%4];"
                 : "=r"(r0), "=r"(r1), "=r"(r2), "=r"(r3) : "r"(a));
}
__device__ __forceinline__ void mma16816(float* c, const uint32_t* a,
                                         const uint32_t* b) {
    asm volatile(
        "mma.sync.aligned.m16n8k16.row.col.f32.bf16.bf16.f32 "
        "{%0,%1,%2,%3}, {%4,%5,%6,%7}, {%8,%9}, {%0,%1,%2,%3};"
        : "+f"(c[0]), "+f"(c[1]), "+f"(c[2]), "+f"(c[3])
        : "r"(a[0]), "r"(a[1]), "r"(a[2]), "r"(a[3]), "r"(b[0]), "r"(b[1]));
}
__device__ __forceinline__ void split_f32(float v, __nv_bfloat16& h, __nv_bfloat16& l) {
    h = __float2bfloat16(v);
    l = __float2bfloat16(v - __bfloat162float(h));
}

// ===== launch 0: fused prep (pad/split + idx detect + zero dot) + bot L0 ====
__device__ __forceinline__ void padsplit_one(const float* W, __nv_bfloat16* Wh,
                                             __nv_bfloat16* Wl, int i,
                                             int Kin, int Kpad) {
    const int n = i / Kpad;
    const int k = i - n * Kpad;
    const float v = (k < Kin) ? W[n * Kin + k] : 0.f;
    __nv_bfloat16 h, l; split_f32(v, h, l);
    Wh[i] = h; Wl[i] = l;
}

__global__ void __launch_bounds__(256) prep_bot0_kernel(
    const float* __restrict__ X, const float* __restrict__ bW0,
    const float* __restrict__ bb0,
    __nv_bfloat16* __restrict__ Yh, __nv_bfloat16* __restrict__ Yl,
    const float* __restrict__ bW1, const float* __restrict__ bW2,
    const float* __restrict__ tW0, const float* __restrict__ tW1,
    const int* __restrict__ lsi32,
    __nv_bfloat16* __restrict__ bW1h, __nv_bfloat16* __restrict__ bW1l,
    __nv_bfloat16* __restrict__ bW2h, __nv_bfloat16* __restrict__ bW2l,
    __nv_bfloat16* __restrict__ tW0h, __nv_bfloat16* __restrict__ tW0l,
    __nv_bfloat16* __restrict__ tW1h, __nv_bfloat16* __restrict__ tW1l,
    float* __restrict__ dotAcc)
{
    const int bid = blockIdx.x;
    const int tid = threadIdx.x;
    if (bid < 64) dotAcc[bid * 256 + tid] = 0.f;   // zero fused-dot accumulator
    if (bid < 1024) {
        __shared__ float sW[512 * 13];
        __shared__ float sb[512];
        __shared__ float sx[16 * 13];
        const int r0 = bid * 16;
        for (int i = tid; i < 512 * 13; i += 256) sW[i] = bW0[i];
        for (int i = tid; i < 512; i += 256) sb[i] = bb0[i];
        for (int i = tid; i < 16 * 13; i += 256) sx[i] = X[r0 * 13 + i];
        __syncthreads();
        for (int o = tid; o < 16 * 512; o += 256) {
            const int r = o >> 9;
            const int c = o & 511;
            float acc = sb[c];
            #pragma unroll
            for (int k = 0; k < 13; k++) acc += sx[r * 13 + k] * sW[c * 13 + k];
            acc = fmaxf(acc, 0.f);
            __nv_bfloat16 h, l; split_f32(acc, h, l);
            const size_t idx = (size_t)(r0 + r) * 512 + c;
            Yh[idx] = h; Yl[idx] = l;
        }
        return;
    }
    if (bid == 3008) {
        if (tid < 32) {
            int any = 0;
            for (int k = tid; k < 2048; k += 32)
                if (lsi32[2 * k + 1] != 0) any = 1;
            any = __any_sync(0xFFFFFFFFu, any);
            if (tid == 0) g_idx_is64 = any ? 0 : 1;
        }
        return;
    }
    const int i = (bid - 1024) * 256 + tid;
    if (i < 131072) {
        padsplit_one(bW1, bW1h, bW1l, i, 512, 512);
    } else if (i < 147456) {
        padsplit_one(bW2, bW2h, bW2l, i - 131072, 256, 256);
    } else if (i < 376832) {
        padsplit_one(tW0, tW0h, tW0l, i - 147456, 415, 448);
    } else {
        padsplit_one(tW1, tW1h, tW1l, i - 376832, 512, 512);
    }
}

// ======================= mma.sync bf16x3 GEMM (NT=64, 2 CTA/SM) =============
// Optional fused final-dot epilogue: when dotOut != nullptr, instead of
// storing C it accumulates relu(C[m][:]) . Wdot into dotOut[m] via atomicAdd.
#define STG 49152u
__device__ __forceinline__ uint32_t swz(int row, int chunk) {
    return (uint32_t)(row * 128 + ((chunk ^ (row & 7)) * 16));
}

__global__ void __launch_bounds__(256) gemm_mma(
    const __nv_bfloat16* __restrict__ Ah, const __nv_bfloat16* __restrict__ Al,
    const __nv_bfloat16* __restrict__ Wh, const __nv_bfloat16* __restrict__ Wl,
    const float* __restrict__ bias, int K, int NC,
    float* __restrict__ Cf,
    __nv_bfloat16* __restrict__ Ch, __nv_bfloat16* __restrict__ Cl,
    int ldc, int relu, int splitOut,
    const float* __restrict__ Wdot, float* __restrict__ dotOut)
{
    extern __shared__ char smem[];
    const uint32_t sb = smem_u32(smem);
    const int tid  = threadIdx.x;
    const int lane = tid & 31;
    const int wid  = tid >> 5;
    const int wm   = wid >> 1;
    const int wn   = wid & 1;
    const int m0 = blockIdx.y * 128;
    const int n0 = blockIdx.x * 64;
    const size_t rowB = (size_t)K * 2;

    const char* gAh = (const char*)Ah + (size_t)m0 * rowB;
    const char* gAl = (const char*)Al + (size_t)m0 * rowB;
    const char* gWh = (const char*)Wh + (size_t)n0 * rowB;
    const char* gWl = (const char*)Wl + (size_t)n0 * rowB;

    float acc[2][4][4];
    #pragma unroll
    for (int t = 0; t < 2; t++)
        #pragma unroll
        for (int u = 0; u < 4; u++)
            #pragma unroll
            for (int v = 0; v < 4; v++) acc[t][u][v] = 0.f;

    auto load_stage = [&](int c) {
        const uint32_t so = sb + (uint32_t)(c & 1) * STG;
        const size_t kb = (size_t)c * 128;
        #pragma unroll
        for (int i = 0; i < 4; i++) {
            const int e = tid + i * 256;
            const int row = e >> 3;
            const int ch  = e & 7;
            const size_t gs = (size_t)row * rowB + kb + ch * 16;
            const uint32_t d = swz(row, ch);
            cpa16(so + d,          gAh + gs);
            cpa16(so + 16384 + d,  gAl + gs);
        }
        #pragma unroll
        for (int i = 0; i < 2; i++) {
            const int e = tid + i * 256;
            const int row = e >> 3;
            const int ch  = e & 7;
            const size_t gs = (size_t)row * rowB + kb + ch * 16;
            const uint32_t d = swz(row, ch);
            cpa16(so + 32768 + d, gWh + gs);
            cpa16(so + 40960 + d, gWl + gs);
        }
        cpa_commit();
    };

    load_stage(0);
    for (int c = 0; c < NC; ++c) {
        if (c + 1 < NC) load_stage(c + 1);
        if (c + 1 < NC) cpa_wait1(); else cpa_wait0();
        __syncthreads();

        const uint32_t so = sb + (uint32_t)(c & 1) * STG;
        const uint32_t sAhB = so, sAlB = so + 16384;
        const uint32_t sWhB = so + 32768, sWlB = so + 40960;

        #pragma unroll
        for (int kk = 0; kk < 4; kk++) {
            uint32_t ah[2][4], al[2][4], bh[8], bl[8];
            #pragma unroll
            for (int t = 0; t < 2; t++) {
                const int row = wm * 32 + t * 16 + (lane & 15);
                const int ch  = kk * 2 + (lane >> 4);
                const uint32_t d = swz(row, ch);
                ldm_x4(sAhB + d, ah[t][0], ah[t][1], ah[t][2], ah[t][3]);
                ldm_x4(sAlB + d, al[t][0], al[t][1], al[t][2], al[t][3]);
            }
            #pragma unroll
            for (int p = 0; p < 2; p++) {
                const int row = wn * 32 + p * 16 + ((lane >> 4) & 1) * 8 + (lane & 7);
                const int ch  = kk * 2 + ((lane >> 3) & 1);
                const uint32_t d = swz(row, ch);
                ldm_x4(sWhB + d, bh[p * 4 + 0], bh[p * 4 + 1], bh[p * 4 + 2], bh[p * 4 + 3]);
                ldm_x4(sWlB + d, bl[p * 4 + 0], bl[p * 4 + 1], bl[p * 4 + 2], bl[p * 4 + 3]);
            }
            #pragma unroll
            for (int t = 0; t < 2; t++)
                #pragma unroll
                for (int u = 0; u < 4; u++) {
                    mma16816(acc[t][u], ah[t], &bh[u * 2]);
                    mma16816(acc[t][u], ah[t], &bl[u * 2]);
                    mma16816(acc[t][u], al[t], &bh[u * 2]);
                }
        }
        __syncthreads();
    }

    float dsum[2][2] = {{0.f, 0.f}, {0.f, 0.f}};
    #pragma unroll
    for (int t = 0; t < 2; t++) {
        const int rbase = m0 + wm * 32 + t * 16 + (lane >> 2);
        #pragma unroll
        for (int u = 0; u < 4; u++) {
            const int gn = n0 + wn * 32 + u * 8 + (lane & 3) * 2;
            const float b0 = __ldg(&bias[gn]);
            const float b1 = __ldg(&bias[gn + 1]);
            #pragma unroll
            for (int h = 0; h < 2; h++) {
                float v0 = acc[t][u][h * 2 + 0] + b0;
                float v1 = acc[t][u][h * 2 + 1] + b1;
                if (relu) { v0 = fmaxf(v0, 0.f); v1 = fmaxf(v1, 0.f); }
                if (dotOut) {
                    dsum[t][h] += v0 * __ldg(&Wdot[gn]) + v1 * __ldg(&Wdot[gn + 1]);
                } else {
                    const size_t idx = (size_t)(rbase + h * 8) * ldc + gn;
                    if (splitOut) {
                        __nv_bfloat16 h0, l0, h1, l1;
                        split_f32(v0, h0, l0); split_f32(v1, h1, l1);
                        *reinterpret_cast<__nv_bfloat162*>(Ch + idx) = __halves2bfloat162(h0, h1);
                        *reinterpret_cast<__nv_bfloat162*>(Cl + idx) = __halves2bfloat162(l0, l1);
                    } else {
                        *reinterpret_cast<float2*>(Cf + idx) = make_float2(v0, v1);
                    }
                }
            }
        }
        if (dotOut) {
            atomicAdd(&dotOut[rbase],     dsum[t][0]);
            atomicAdd(&dotOut[rbase + 8], dsum[t][1]);
        }
    }
}

// ======== fused gather + tensor-core interaction (R12 config) ==============
__global__ void __launch_bounds__(128) gather_interact_kernel(
    const float* __restrict__ x, const float* __restrict__ emb,
    const void* __restrict__ lsi,
    __nv_bfloat16* __restrict__ Rh, __nv_bfloat16* __restrict__ Rl)
{
    __shared__ __nv_bfloat16 sTh[32 * 64];   // 32 rows x 128B (swizzled)
    __shared__ __nv_bfloat16 sTl[32 * 64];
    const int b   = blockIdx.x;
    const int tid = threadIdx.x;
    const int hw  = tid >> 4;
    const int lh  = tid & 15;
    const int is64 = g_idx_is64;
    const long long* ip64 = (const long long*)lsi;
    const int*       ip32 = (const int*)lsi;
    const uint32_t th = smem_u32(sTh);
    const uint32_t tl = smem_u32(sTl);

    for (int i = tid; i < 40; i += 128) {
        reinterpret_cast<uint4*>(sTh)[27 * 8 + i] = make_uint4(0, 0, 0, 0);
        reinterpret_cast<uint4*>(sTl)[27 * 8 + i] = make_uint4(0, 0, 0, 0);
    }

    if (tid < 16) {
        float4 v = *reinterpret_cast<const float4*>(x + (size_t)b * 64 + lh * 4);
        __nv_bfloat16 h0, l0, h1, l1, h2, l2, h3, l3;
        split_f32(v.x, h0, l0); split_f32(v.y, h1, l1);
        split_f32(v.z, h2, l2); split_f32(v.w, h3, l3);
        *reinterpret_cast<__nv_bfloat162*>(&sTh[lh * 4])     = __halves2bfloat162(h0, h1);
        *reinterpret_cast<__nv_bfloat162*>(&sTh[lh * 4 + 2]) = __halves2bfloat162(h2, h3);
        *reinterpret_cast<__nv_bfloat162*>(&sTl[lh * 4])     = __halves2bfloat162(l0, l1);
        *reinterpret_cast<__nv_bfloat162*>(&sTl[lh * 4 + 2]) = __halves2bfloat162(l2, l3);
    }

    #pragma unroll
    for (int r = 0; r < 4; r++) {
        const int t = hw + r * 8;
        if (t >= NTAB) break;
        const size_t ibase = ((size_t)t * B_SZ + b) * 4;
        const float* tb = emb + (size_t)t * (VOCAB * EMB_D);
        float4 acc = make_float4(0.f, 0.f, 0.f, 0.f);
        #pragma unroll
        for (int l = 0; l < 4; l++) {
            unsigned int ix = is64 ? (unsigned int)ip64[ibase + l]
                                   : (unsigned int)ip32[ibase + l];
            if (ix >= VOCAB) ix = VOCAB - 1;
            const float4* row = reinterpret_cast<const float4*>(tb + (size_t)ix * EMB_D);
            float4 v = __ldg(row + lh);
            acc.x += v.x; acc.y += v.y; acc.z += v.z; acc.w += v.w;
        }
        __nv_bfloat16 h0, l0, h1, l1, h2, l2, h3, l3;
        split_f32(acc.x, h0, l0); split_f32(acc.y, h1, l1);
        split_f32(acc.z, h2, l2); split_f32(acc.w, h3, l3);
        const int row = 1 + t;
        const uint32_t off = swz(row, lh >> 1) + (lh & 1) * 8;
        *reinterpret_cast<__nv_bfloat162*>((char*)sTh + off)     = __halves2bfloat162(h0, h1);
        *reinterpret_cast<__nv_bfloat162*>((char*)sTh + off + 4) = __halves2bfloat162(h2, h3);
        *reinterpret_cast<__nv_bfloat162*>((char*)sTl + off)     = __halves2bfloat162(l0, l1);
        *reinterpret_cast<__nv_bfloat162*>((char*)sTl + off + 4) = __halves2bfloat162(l2, l3);
    }
    __syncthreads();

    __nv_bfloat16* Rbh = Rh + (size_t)b * 448;
    __nv_bfloat16* Rbl = Rl + (size_t)b * 448;

    if (tid >= 64 && tid < 128) {
        const int c = tid - 64;
        Rbh[c] = sTh[c]; Rbl[c] = sTl[c];
    }
    for (int c = 415 + tid; c < 448; c += 128) {
        Rbh[c] = __float2bfloat16(0.f); Rbl[c] = __float2bfloat16(0.f);
    }

    const int wid  = tid >> 5;
    const int lane = tid & 31;
    if (wid < 2) {
        float acc[4][4];
        #pragma unroll
        for (int u = 0; u < 4; u++)
            #pragma unroll
            for (int v = 0; v < 4; v++) acc[u][v] = 0.f;

        #pragma unroll
        for (int kk = 0; kk < 4; kk++) {
            uint32_t ah[4], al[4], bh[8], bl[8];
            {
                const int row = wid * 16 + (lane & 15);
                const int ch  = kk * 2 + (lane >> 4);
                const uint32_t d = swz(row, ch);
                ldm_x4(th + d, ah[0], ah[1], ah[2], ah[3]);
                ldm_x4(tl + d, al[0], al[1], al[2], al[3]);
            }
            #pragma unroll
            for (int p = 0; p < 2; p++) {
                const int row = p * 16 + ((lane >> 4) & 1) * 8 + (lane & 7);
                const int ch  = kk * 2 + ((lane >> 3) & 1);
                const uint32_t d = swz(row, ch);
                ldm_x4(th + d, bh[p * 4 + 0], bh[p * 4 + 1], bh[p * 4 + 2], bh[p * 4 + 3]);
                ldm_x4(tl + d, bl[p * 4 + 0], bl[p * 4 + 1], bl[p * 4 + 2], bl[p * 4 + 3]);
            }
            #pragma unroll
            for (int u = 0; u < 4; u++) {
                mma16816(acc[u], ah, &bh[u * 2]);
                mma16816(acc[u], ah, &bl[u * 2]);
                mma16816(acc[u], al, &bh[u * 2]);
            }
        }

        const int ib = wid * 16 + (lane >> 2);
        #pragma unroll
        for (int u = 0; u < 4; u++) {
            const int jn = u * 8 + (lane & 3) * 2;
            #pragma unroll
            for (int h = 0; h < 2; h++) {
                const int i = ib + h * 8;
                #pragma unroll
                for (int e = 0; e < 2; e++) {
                    const int j = jn + e;
                    if (i > j && i < 27 && j < 27) {
                        __nv_bfloat16 hh, ll;
                        split_f32(acc[u][h * 2 + e], hh, ll);
                        const int p = i * (i - 1) / 2 + j;
                        Rbh[64 + p] = hh; Rbl[64 + p] = ll;
                    }
                }
            }
        }
    }
}

// ======================= final sigmoid ======================================
__global__ void __launch_bounds__(256) sigmoid_kernel(
    const float* __restrict__ dot, const float* __restrict__ bias,
    float* __restrict__ out)
{
    const int i = blockIdx.x * 256 + threadIdx.x;
    const float v = dot[i] + bias[0];
    out[i] = 1.f / (1.f + expf(-v));
}

// ======================= launch =============================================
extern "C" void kernel_launch(void* const* d_in, const int* in_sizes, int n_in,
                              void* d_out, int out_size)
{
    (void)n_in; (void)out_size;
    const float* dense_x = (const float*)d_in[0];
    const void*  lsi     = d_in[2];
    const float* emb     = (const float*)d_in[3];

    const float *bW0, *bb0, *bW1, *bb1, *bW2, *bb2;
    const float *tW0, *tb0, *tW1, *tb1, *tW2, *tb2;
    if (in_sizes[6] == 512 * 415) {
        bW0 = (const float*)d_in[4];  bb0 = (const float*)d_in[5];
        tW0 = (const float*)d_in[6];  tb0 = (const float*)d_in[7];
        bW1 = (const float*)d_in[8];  bb1 = (const float*)d_in[9];
        tW1 = (const float*)d_in[10]; tb1 = (const float*)d_in[11];
        bW2 = (const float*)d_in[12]; bb2 = (const float*)d_in[13];
        tW2 = (const float*)d_in[14]; tb2 = (const float*)d_in[15];
    } else {
        bW0 = (const float*)d_in[4];  bb0 = (const float*)d_in[5];
        bW1 = (const float*)d_in[6];  bb1 = (const float*)d_in[7];
        bW2 = (const float*)d_in[8];  bb2 = (const float*)d_in[9];
        tW0 = (const float*)d_in[10]; tb0 = (const float*)d_in[11];
        tW1 = (const float*)d_in[12]; tb1 = (const float*)d_in[13];
        tW2 = (const float*)d_in[14]; tb2 = (const float*)d_in[15];
    }

    float *x, *dot;
    __nv_bfloat16 *x1h, *x1l, *x2h, *x2l, *Rh, *Rl, *z1h, *z1l;
    __nv_bfloat16 *bW1h, *bW1l, *bW2h, *bW2l, *tW0h, *tW0l, *tW1h, *tW1l;
    cudaGetSymbolAddress((void**)&x,    g_x);
    cudaGetSymbolAddress((void**)&dot,  g_dot);
    cudaGetSymbolAddress((void**)&x1h,  g_x1h);  cudaGetSymbolAddress((void**)&x1l, g_x1l);
    cudaGetSymbolAddress((void**)&x2h,  g_x2h);  cudaGetSymbolAddress((void**)&x2l, g_x2l);
    cudaGetSymbolAddress((void**)&Rh,   g_Rh);   cudaGetSymbolAddress((void**)&Rl,  g_Rl);
    cudaGetSymbolAddress((void**)&z1h,  g_z1h);  cudaGetSymbolAddress((void**)&z1l, g_z1l);
    cudaGetSymbolAddress((void**)&bW1h, g_bW1h); cudaGetSymbolAddress((void**)&bW1l, g_bW1l);
    cudaGetSymbolAddress((void**)&bW2h, g_bW2h); cudaGetSymbolAddress((void**)&bW2l, g_bW2l);
    cudaGetSymbolAddress((void**)&tW0h, g_tW0h); cudaGetSymbolAddress((void**)&tW0l, g_tW0l);
    cudaGetSymbolAddress((void**)&tW1h, g_tW1h); cudaGetSymbolAddress((void**)&tW1l, g_tW1l);

    const int SMEM = 2 * 49152;   // 96KB -> 2 CTA/SM
    cudaFuncSetAttribute(gemm_mma, cudaFuncAttributeMaxDynamicSharedMemorySize, SMEM);

    // launch 0: fused prep (pad/split + detect + zero dot) + bot layer 0
    prep_bot0_kernel<<<3009, 256>>>(dense_x, bW0, bb0, x1h, x1l,
                                    bW1, bW2, tW0, tW1, (const int*)lsi,
                                    bW1h, bW1l, bW2h, bW2l,
                                    tW0h, tW0l, tW1h, tW1l, dot);

    // launches 1-2: rest of bottom MLP -> compact x[B,64]
    gemm_mma<<<dim3(4, 128), 256, SMEM>>>(x1h, x1l, bW1h, bW1l, bb1, 512, 8,
                                          nullptr, x2h, x2l, 256, 1, 1,
                                          nullptr, nullptr);
    gemm_mma<<<dim3(1, 128), 256, SMEM>>>(x2h, x2l, bW2h, bW2l, bb2, 256, 4,
                                          x, nullptr, nullptr, 64, 1, 0,
                                          nullptr, nullptr);

    // launch 3: fused gather + tensor-core interaction -> split R[B,448]
    gather_interact_kernel<<<B_SZ, 128>>>(x, emb, lsi, Rh, Rl);

    // launches 4-5: top MLP (t1 fuses the final 256->1 dot via atomics)
    gemm_mma<<<dim3(8, 128), 256, SMEM>>>(Rh, Rl, tW0h, tW0l, tb0, 448, 7,
                                          nullptr, z1h, z1l, 512, 1, 1,
                                          nullptr, nullptr);
    gemm_mma<<<dim3(4, 128), 256, SMEM>>>(z1h, z1l, tW1h, tW1l, tb1, 512, 8,
                                          nullptr, nullptr, nullptr, 256, 1, 0,
                                          tW2, dot);

    // launch 6: sigmoid
    sigmoid_kernel<<<B_SZ / 256, 256>>>(dot, tb2, (float*)d_out);
}

// round 15
// speedup vs baseline: 1.0307x; 1.0022x over previous
#include <cuda_runtime.h>
#include <cuda_bf16.h>
#include <math.h>
#include <stdint.h>

#define B_SZ   16384
#define NTAB   26
#define VOCAB  100000
#define EMB_D  64

// ======================= scratch (device globals) ==========================
__device__ __align__(256) float g_x  [B_SZ * 64];           // bot MLP out fp32
__device__ __align__(256) float g_dot[B_SZ];                // fused final-dot acc

__device__ __align__(256) __nv_bfloat16 g_x1h[B_SZ * 512];
__device__ __align__(256) __nv_bfloat16 g_x1l[B_SZ * 512];
__device__ __align__(256) __nv_bfloat16 g_x2h[B_SZ * 256];
__device__ __align__(256) __nv_bfloat16 g_x2l[B_SZ * 256];
__device__ __align__(256) __nv_bfloat16 g_Rh [B_SZ * 448];
__device__ __align__(256) __nv_bfloat16 g_Rl [B_SZ * 448];
__device__ __align__(256) __nv_bfloat16 g_z1h[B_SZ * 512];
__device__ __align__(256) __nv_bfloat16 g_z1l[B_SZ * 512];

__device__ __align__(256) __nv_bfloat16 g_bW1h[256 * 512];
__device__ __align__(256) __nv_bfloat16 g_bW1l[256 * 512];
__device__ __align__(256) __nv_bfloat16 g_bW2h[64 * 256];
__device__ __align__(256) __nv_bfloat16 g_bW2l[64 * 256];
__device__ __align__(256) __nv_bfloat16 g_tW0h[512 * 448];
__device__ __align__(256) __nv_bfloat16 g_tW0l[512 * 448];
__device__ __align__(256) __nv_bfloat16 g_tW1h[256 * 512];
__device__ __align__(256) __nv_bfloat16 g_tW1l[256 * 512];

__device__ int g_idx_is64;

// ======================= helpers ============================================
__device__ __forceinline__ uint32_t smem_u32(const void* p) {
    uint32_t a;
    asm("{ .reg .u64 t; cvta.to.shared.u64 t, %1; cvt.u32.u64 %0, t; }"
        : "=r"(a) : "l"(p));
    return a;
}
__device__ __forceinline__ void cpa16(uint32_t saddr, const void* g) {
    asm volatile("cp.async.cg.shared.global [%0], [%1], 16;" :: "r"(saddr), "l"(g));
}
__device__ __forceinline__ void cpa_commit() {
    asm volatile("cp.async.commit_group;" ::: "memory");
}
__device__ __forceinline__ void cpa_wait0() {
    asm volatile("cp.async.wait_group 0;" ::: "memory");
}
__device__ __forceinline__ void ldm_x4(uint32_t a, uint32_t& r0, uint32_t& r1,
                                       uint32_t& r2, uint32_t& r3) {
    asm volatile("ldmatrix.sync.aligned.m8n8.x4.shared.b16 {%0,%1,%2,%3}, [%4];"
                 : "=r"(r0), "=r"(r1), "=r"(r2), "=r"(r3) : "r"(a));
}
__device__ __forceinline__ void mma16816(float* c, const uint32_t* a,
                                         const uint32_t* b) {
    asm volatile(
        "mma.sync.aligned.m16n8k16.row.col.f32.bf16.bf16.f32 "
        "{%0,%1,%2,%3}, {%4,%5,%6,%7}, {%8,%9}, {%0,%1,%2,%3};"
        : "+f"(c[0]), "+f"(c[1]), "+f"(c[2]), "+f"(c[3])
        : "r"(a[0]), "r"(a[1]), "r"(a[2]), "r"(a[3]), "r"(b[0]), "r"(b[1]));
}
__device__ __forceinline__ void split_f32(float v, __nv_bfloat16& h, __nv_bfloat16& l) {
    h = __float2bfloat16(v);
    l = __float2bfloat16(v - __bfloat162float(h));
}

// ===== launch 0: fused prep (pad/split + idx detect + zero dot) + bot L0 ====
__device__ __forceinline__ void padsplit_one(const float* W, __nv_bfloat16* Wh,
                                             __nv_bfloat16* Wl, int i,
                                             int Kin, int Kpad) {
    const int n = i / Kpad;
    const int k = i - n * Kpad;
    const float v = (k < Kin) ? W[n * Kin + k] : 0.f;
    __nv_bfloat16 h, l; split_f32(v, h, l);
    Wh[i] = h; Wl[i] = l;
}

__global__ void __launch_bounds__(256) prep_bot0_kernel(
    const float* __restrict__ X, const float* __restrict__ bW0,
    const float* __restrict__ bb0,
    __nv_bfloat16* __restrict__ Yh, __nv_bfloat16* __restrict__ Yl,
    const float* __restrict__ bW1, const float* __restrict__ bW2,
    const float* __restrict__ tW0, const float* __restrict__ tW1,
    const int* __restrict__ lsi32,
    __nv_bfloat16* __restrict__ bW1h, __nv_bfloat16* __restrict__ bW1l,
    __nv_bfloat16* __restrict__ bW2h, __nv_bfloat16* __restrict__ bW2l,
    __nv_bfloat16* __restrict__ tW0h, __nv_bfloat16* __restrict__ tW0l,
    __nv_bfloat16* __restrict__ tW1h, __nv_bfloat16* __restrict__ tW1l,
    float* __restrict__ dotAcc)
{
    const int bid = blockIdx.x;
    const int tid = threadIdx.x;
    if (bid < 64) dotAcc[bid * 256 + tid] = 0.f;   // zero fused-dot accumulator
    if (bid < 1024) {
        __shared__ float sW[512 * 13];
        __shared__ float sb[512];
        __shared__ float sx[16 * 13];
        const int r0 = bid * 16;
        for (int i = tid; i < 512 * 13; i += 256) sW[i] = bW0[i];
        for (int i = tid; i < 512; i += 256) sb[i] = bb0[i];
        for (int i = tid; i < 16 * 13; i += 256) sx[i] = X[r0 * 13 + i];
        __syncthreads();
        for (int o = tid; o < 16 * 512; o += 256) {
            const int r = o >> 9;
            const int c = o & 511;
            float acc = sb[c];
            #pragma unroll
            for (int k = 0; k < 13; k++) acc += sx[r * 13 + k] * sW[c * 13 + k];
            acc = fmaxf(acc, 0.f);
            __nv_bfloat16 h, l; split_f32(acc, h, l);
            const size_t idx = (size_t)(r0 + r) * 512 + c;
            Yh[idx] = h; Yl[idx] = l;
        }
        return;
    }
    if (bid == 3008) {
        if (tid < 32) {
            int any = 0;
            for (int k = tid; k < 2048; k += 32)
                if (lsi32[2 * k + 1] != 0) any = 1;
            any = __any_sync(0xFFFFFFFFu, any);
            if (tid == 0) g_idx_is64 = any ? 0 : 1;
        }
        return;
    }
    const int i = (bid - 1024) * 256 + tid;
    if (i < 131072) {
        padsplit_one(bW1, bW1h, bW1l, i, 512, 512);
    } else if (i < 147456) {
        padsplit_one(bW2, bW2h, bW2l, i - 131072, 256, 256);
    } else if (i < 376832) {
        padsplit_one(tW0, tW0h, tW0l, i - 147456, 415, 448);
    } else {
        padsplit_one(tW1, tW1h, tW1l, i - 376832, 512, 512);
    }
}

// ============ mma.sync bf16x3 GEMM (NT=64, 2 CTA/SM, 1 sync/chunk) =========
// Optional fused final-dot epilogue: when dotOut != nullptr, instead of
// storing C it accumulates relu(C[m][:]) . Wdot into dotOut[m] via atomicAdd.
#define STG 49152u
__device__ __forceinline__ uint32_t swz(int row, int chunk) {
    return (uint32_t)(row * 128 + ((chunk ^ (row & 7)) * 16));
}

__global__ void __launch_bounds__(256) gemm_mma(
    const __nv_bfloat16* __restrict__ Ah, const __nv_bfloat16* __restrict__ Al,
    const __nv_bfloat16* __restrict__ Wh, const __nv_bfloat16* __restrict__ Wl,
    const float* __restrict__ bias, int K, int NC,
    float* __restrict__ Cf,
    __nv_bfloat16* __restrict__ Ch, __nv_bfloat16* __restrict__ Cl,
    int ldc, int relu, int splitOut,
    const float* __restrict__ Wdot, float* __restrict__ dotOut)
{
    extern __shared__ char smem[];
    const uint32_t sb = smem_u32(smem);
    const int tid  = threadIdx.x;
    const int lane = tid & 31;
    const int wid  = tid >> 5;
    const int wm   = wid >> 1;
    const int wn   = wid & 1;
    const int m0 = blockIdx.y * 128;
    const int n0 = blockIdx.x * 64;
    const size_t rowB = (size_t)K * 2;

    const char* gAh = (const char*)Ah + (size_t)m0 * rowB;
    const char* gAl = (const char*)Al + (size_t)m0 * rowB;
    const char* gWh = (const char*)Wh + (size_t)n0 * rowB;
    const char* gWl = (const char*)Wl + (size_t)n0 * rowB;

    float acc[2][4][4];
    #pragma unroll
    for (int t = 0; t < 2; t++)
        #pragma unroll
        for (int u = 0; u < 4; u++)
            #pragma unroll
            for (int v = 0; v < 4; v++) acc[t][u][v] = 0.f;

    auto load_stage = [&](int c) {
        const uint32_t so = sb + (uint32_t)(c & 1) * STG;
        const size_t kb = (size_t)c * 128;
        #pragma unroll
        for (int i = 0; i < 4; i++) {
            const int e = tid + i * 256;
            const int row = e >> 3;
            const int ch  = e & 7;
            const size_t gs = (size_t)row * rowB + kb + ch * 16;
            const uint32_t d = swz(row, ch);
            cpa16(so + d,          gAh + gs);
            cpa16(so + 16384 + d,  gAl + gs);
        }
        #pragma unroll
        for (int i = 0; i < 2; i++) {
            const int e = tid + i * 256;
            const int row = e >> 3;
            const int ch  = e & 7;
            const size_t gs = (size_t)row * rowB + kb + ch * 16;
            const uint32_t d = swz(row, ch);
            cpa16(so + 32768 + d, gWh + gs);
            cpa16(so + 40960 + d, gWl + gs);
        }
        cpa_commit();
    };

    // single-barrier double-buffered mainloop:
    //   wait(own stage-c copies) -> sync (stage-c visible to all AND all warps
    //   done computing c-1, so buffer (c+1)==(c-1) is free) -> issue load(c+1)
    //   -> compute(c)
    load_stage(0);
    for (int c = 0; c < NC; ++c) {
        cpa_wait0();
        __syncthreads();
        if (c + 1 < NC) load_stage(c + 1);

        const uint32_t so = sb + (uint32_t)(c & 1) * STG;
        const uint32_t sAhB = so, sAlB = so + 16384;
        const uint32_t sWhB = so + 32768, sWlB = so + 40960;

        #pragma unroll
        for (int kk = 0; kk < 4; kk++) {
            uint32_t ah[2][4], al[2][4], bh[8], bl[8];
            #pragma unroll
            for (int t = 0; t < 2; t++) {
                const int row = wm * 32 + t * 16 + (lane & 15);
                const int ch  = kk * 2 + (lane >> 4);
                const uint32_t d = swz(row, ch);
                ldm_x4(sAhB + d, ah[t][0], ah[t][1], ah[t][2], ah[t][3]);
                ldm_x4(sAlB + d, al[t][0], al[t][1], al[t][2], al[t][3]);
            }
            #pragma unroll
            for (int p = 0; p < 2; p++) {
                const int row = wn * 32 + p * 16 + ((lane >> 4) & 1) * 8 + (lane & 7);
                const int ch  = kk * 2 + ((lane >> 3) & 1);
                const uint32_t d = swz(row, ch);
                ldm_x4(sWhB + d, bh[p * 4 + 0], bh[p * 4 + 1], bh[p * 4 + 2], bh[p * 4 + 3]);
                ldm_x4(sWlB + d, bl[p * 4 + 0], bl[p * 4 + 1], bl[p * 4 + 2], bl[p * 4 + 3]);
            }
            #pragma unroll
            for (int t = 0; t < 2; t++)
                #pragma unroll
                for (int u = 0; u < 4; u++) {
                    mma16816(acc[t][u], ah[t], &bh[u * 2]);
                    mma16816(acc[t][u], ah[t], &bl[u * 2]);
                    mma16816(acc[t][u], al[t], &bh[u * 2]);
                }
        }
    }

    float dsum[2][2] = {{0.f, 0.f}, {0.f, 0.f}};
    #pragma unroll
    for (int t = 0; t < 2; t++) {
        const int rbase = m0 + wm * 32 + t * 16 + (lane >> 2);
        #pragma unroll
        for (int u = 0; u < 4; u++) {
            const int gn = n0 + wn * 32 + u * 8 + (lane & 3) * 2;
            const float b0 = __ldg(&bias[gn]);
            const float b1 = __ldg(&bias[gn + 1]);
            #pragma unroll
            for (int h = 0; h < 2; h++) {
                float v0 = acc[t][u][h * 2 + 0] + b0;
                float v1 = acc[t][u][h * 2 + 1] + b1;
                if (relu) { v0 = fmaxf(v0, 0.f); v1 = fmaxf(v1, 0.f); }
                if (dotOut) {
                    dsum[t][h] += v0 * __ldg(&Wdot[gn]) + v1 * __ldg(&Wdot[gn + 1]);
                } else {
                    const size_t idx = (size_t)(rbase + h * 8) * ldc + gn;
                    if (splitOut) {
                        __nv_bfloat16 h0, l0, h1, l1;
                        split_f32(v0, h0, l0); split_f32(v1, h1, l1);
                        *reinterpret_cast<__nv_bfloat162*>(Ch + idx) = __halves2bfloat162(h0, h1);
                        *reinterpret_cast<__nv_bfloat162*>(Cl + idx) = __halves2bfloat162(l0, l1);
                    } else {
                        *reinterpret_cast<float2*>(Cf + idx) = make_float2(v0, v1);
                    }
                }
            }
        }
        if (dotOut) {
            atomicAdd(&dotOut[rbase],     dsum[t][0]);
            atomicAdd(&dotOut[rbase + 8], dsum[t][1]);
        }
    }
}

// ======== fused gather + tensor-core interaction (R12 config) ==============
__global__ void __launch_bounds__(128) gather_interact_kernel(
    const float* __restrict__ x, const float* __restrict__ emb,
    const void* __restrict__ lsi,
    __nv_bfloat16* __restrict__ Rh, __nv_bfloat16* __restrict__ Rl)
{
    __shared__ __nv_bfloat16 sTh[32 * 64];   // 32 rows x 128B (swizzled)
    __shared__ __nv_bfloat16 sTl[32 * 64];
    const int b   = blockIdx.x;
    const int tid = threadIdx.x;
    const int hw  = tid >> 4;
    const int lh  = tid & 15;
    const int is64 = g_idx_is64;
    const long long* ip64 = (const long long*)lsi;
    const int*       ip32 = (const int*)lsi;
    const uint32_t th = smem_u32(sTh);
    const uint32_t tl = smem_u32(sTl);

    for (int i = tid; i < 40; i += 128) {
        reinterpret_cast<uint4*>(sTh)[27 * 8 + i] = make_uint4(0, 0, 0, 0);
        reinterpret_cast<uint4*>(sTl)[27 * 8 + i] = make_uint4(0, 0, 0, 0);
    }

    if (tid < 16) {
        float4 v = *reinterpret_cast<const float4*>(x + (size_t)b * 64 + lh * 4);
        __nv_bfloat16 h0, l0, h1, l1, h2, l2, h3, l3;
        split_f32(v.x, h0, l0); split_f32(v.y, h1, l1);
        split_f32(v.z, h2, l2); split_f32(v.w, h3, l3);
        *reinterpret_cast<__nv_bfloat162*>(&sTh[lh * 4])     = __halves2bfloat162(h0, h1);
        *reinterpret_cast<__nv_bfloat162*>(&sTh[lh * 4 + 2]) = __halves2bfloat162(h2, h3);
        *reinterpret_cast<__nv_bfloat162*>(&sTl[lh * 4])     = __halves2bfloat162(l0, l1);
        *reinterpret_cast<__nv_bfloat162*>(&sTl[lh * 4 + 2]) = __halves2bfloat162(l2, l3);
    }

    #pragma unroll
    for (int r = 0; r < 4; r++) {
        const int t = hw + r * 8;
        if (t >= NTAB) break;
        const size_t ibase = ((size_t)t * B_SZ + b) * 4;
        const float* tb = emb + (size_t)t * (VOCAB * EMB_D);
        float4 acc = make_float4(0.f, 0.f, 0.f, 0.f);
        #pragma unroll
        for (int l = 0; l < 4; l++) {
            unsigned int ix = is64 ? (unsigned int)ip64[ibase + l]
                                   : (unsigned int)ip32[ibase + l];
            if (ix >= VOCAB) ix = VOCAB - 1;
            const float4* row = reinterpret_cast<const float4*>(tb + (size_t)ix * EMB_D);
            float4 v = __ldg(row + lh);
            acc.x += v.x; acc.y += v.y; acc.z += v.z; acc.w += v.w;
        }
        __nv_bfloat16 h0, l0, h1, l1, h2, l2, h3, l3;
        split_f32(acc.x, h0, l0); split_f32(acc.y, h1, l1);
        split_f32(acc.z, h2, l2); split_f32(acc.w, h3, l3);
        const int row = 1 + t;
        const uint32_t off = swz(row, lh >> 1) + (lh & 1) * 8;
        *reinterpret_cast<__nv_bfloat162*>((char*)sTh + off)     = __halves2bfloat162(h0, h1);
        *reinterpret_cast<__nv_bfloat162*>((char*)sTh + off + 4) = __halves2bfloat162(h2, h3);
        *reinterpret_cast<__nv_bfloat162*>((char*)sTl + off)     = __halves2bfloat162(l0, l1);
        *reinterpret_cast<__nv_bfloat162*>((char*)sTl + off + 4) = __halves2bfloat162(l2, l3);
    }
    __syncthreads();

    __nv_bfloat16* Rbh = Rh + (size_t)b * 448;
    __nv_bfloat16* Rbl = Rl + (size_t)b * 448;

    if (tid >= 64 && tid < 128) {
        const int c = tid - 64;
        Rbh[c] = sTh[c]; Rbl[c] = sTl[c];
    }
    for (int c = 415 + tid; c < 448; c += 128) {
        Rbh[c] = __float2bfloat16(0.f); Rbl[c] = __float2bfloat16(0.f);
    }

    const int wid  = tid >> 5;
    const int lane = tid & 31;
    if (wid < 2) {
        float acc[4][4];
        #pragma unroll
        for (int u = 0; u < 4; u++)
            #pragma unroll
            for (int v = 0; v < 4; v++) acc[u][v] = 0.f;

        #pragma unroll
        for (int kk = 0; kk < 4; kk++) {
            uint32_t ah[4], al[4], bh[8], bl[8];
            {
                const int row = wid * 16 + (lane & 15);
                const int ch  = kk * 2 + (lane >> 4);
                const uint32_t d = swz(row, ch);
                ldm_x4(th + d, ah[0], ah[1], ah[2], ah[3]);
                ldm_x4(tl + d, al[0], al[1], al[2], al[3]);
            }
            #pragma unroll
            for (int p = 0; p < 2; p++) {
                const int row = p * 16 + ((lane >> 4) & 1) * 8 + (lane & 7);
                const int ch  = kk * 2 + ((lane >> 3) & 1);
                const uint32_t d = swz(row, ch);
                ldm_x4(th + d, bh[p * 4 + 0], bh[p * 4 + 1], bh[p * 4 + 2], bh[p * 4 + 3]);
                ldm_x4(tl + d, bl[p * 4 + 0], bl[p * 4 + 1], bl[p * 4 + 2], bl[p * 4 + 3]);
            }
            #pragma unroll
            for (int u = 0; u < 4; u++) {
                mma16816(acc[u], ah, &bh[u * 2]);
                mma16816(acc[u], ah, &bl[u * 2]);
                mma16816(acc[u], al, &bh[u * 2]);
            }
        }

        const int ib = wid * 16 + (lane >> 2);
        #pragma unroll
        for (int u = 0; u < 4; u++) {
            const int jn = u * 8 + (lane & 3) * 2;
            #pragma unroll
            for (int h = 0; h < 2; h++) {
                const int i = ib + h * 8;
                #pragma unroll
                for (int e = 0; e < 2; e++) {
                    const int j = jn + e;
                    if (i > j && i < 27 && j < 27) {
                        __nv_bfloat16 hh, ll;
                        split_f32(acc[u][h * 2 + e], hh, ll);
                        const int p = i * (i - 1) / 2 + j;
                        Rbh[64 + p] = hh; Rbl[64 + p] = ll;
                    }
                }
            }
        }
    }
}

// ======================= final sigmoid ======================================
__global__ void __launch_bounds__(256) sigmoid_kernel(
    const float* __restrict__ dot, const float* __restrict__ bias,
    float* __restrict__ out)
{
    const int i = blockIdx.x * 256 + threadIdx.x;
    const float v = dot[i] + bias[0];
    out[i] = 1.f / (1.f + expf(-v));
}

// ======================= launch =============================================
extern "C" void kernel_launch(void* const* d_in, const int* in_sizes, int n_in,
                              void* d_out, int out_size)
{
    (void)n_in; (void)out_size;
    const float* dense_x = (const float*)d_in[0];
    const void*  lsi     = d_in[2];
    const float* emb     = (const float*)d_in[3];

    const float *bW0, *bb0, *bW1, *bb1, *bW2, *bb2;
    const float *tW0, *tb0, *tW1, *tb1, *tW2, *tb2;
    if (in_sizes[6] == 512 * 415) {
        bW0 = (const float*)d_in[4];  bb0 = (const float*)d_in[5];
        tW0 = (const float*)d_in[6];  tb0 = (const float*)d_in[7];
        bW1 = (const float*)d_in[8];  bb1 = (const float*)d_in[9];
        tW1 = (const float*)d_in[10]; tb1 = (const float*)d_in[11];
        bW2 = (const float*)d_in[12]; bb2 = (const float*)d_in[13];
        tW2 = (const float*)d_in[14]; tb2 = (const float*)d_in[15];
    } else {
        bW0 = (const float*)d_in[4];  bb0 = (const float*)d_in[5];
        bW1 = (const float*)d_in[6];  bb1 = (const float*)d_in[7];
        bW2 = (const float*)d_in[8];  bb2 = (const float*)d_in[9];
        tW0 = (const float*)d_in[10]; tb0 = (const float*)d_in[11];
        tW1 = (const float*)d_in[12]; tb1 = (const float*)d_in[13];
        tW2 = (const float*)d_in[14]; tb2 = (const float*)d_in[15];
    }

    float *x, *dot;
    __nv_bfloat16 *x1h, *x1l, *x2h, *x2l, *Rh, *Rl, *z1h, *z1l;
    __nv_bfloat16 *bW1h, *bW1l, *bW2h, *bW2l, *tW0h, *tW0l, *tW1h, *tW1l;
    cudaGetSymbolAddress((void**)&x,    g_x);
    cudaGetSymbolAddress((void**)&dot,  g_dot);
    cudaGetSymbolAddress((void**)&x1h,  g_x1h);  cudaGetSymbolAddress((void**)&x1l, g_x1l);
    cudaGetSymbolAddress((void**)&x2h,  g_x2h);  cudaGetSymbolAddress((void**)&x2l, g_x2l);
    cudaGetSymbolAddress((void**)&Rh,   g_Rh);   cudaGetSymbolAddress((void**)&Rl,  g_Rl);
    cudaGetSymbolAddress((void**)&z1h,  g_z1h);  cudaGetSymbolAddress((void**)&z1l, g_z1l);
    cudaGetSymbolAddress((void**)&bW1h, g_bW1h); cudaGetSymbolAddress((void**)&bW1l, g_bW1l);
    cudaGetSymbolAddress((void**)&bW2h, g_bW2h); cudaGetSymbolAddress((void**)&bW2l, g_bW2l);
    cudaGetSymbolAddress((void**)&tW0h, g_tW0h); cudaGetSymbolAddress((void**)&tW0l, g_tW0l);
    cudaGetSymbolAddress((void**)&tW1h, g_tW1h); cudaGetSymbolAddress((void**)&tW1l, g_tW1l);

    const int SMEM = 2 * 49152;   // 96KB -> 2 CTA/SM
    cudaFuncSetAttribute(gemm_mma, cudaFuncAttributeMaxDynamicSharedMemorySize, SMEM);

    // launch 0: fused prep (pad/split + detect + zero dot) + bot layer 0
    prep_bot0_kernel<<<3009, 256>>>(dense_x, bW0, bb0, x1h, x1l,
                                    bW1, bW2, tW0, tW1, (const int*)lsi,
                                    bW1h, bW1l, bW2h, bW2l,
                                    tW0h, tW0l, tW1h, tW1l, dot);

    // launches 1-2: rest of bottom MLP -> compact x[B,64]
    gemm_mma<<<dim3(4, 128), 256, SMEM>>>(x1h, x1l, bW1h, bW1l, bb1, 512, 8,
                                          nullptr, x2h, x2l, 256, 1, 1,
                                          nullptr, nullptr);
    gemm_mma<<<dim3(1, 128), 256, SMEM>>>(x2h, x2l, bW2h, bW2l, bb2, 256, 4,
                                          x, nullptr, nullptr, 64, 1, 0,
                                          nullptr, nullptr);

    // launch 3: fused gather + tensor-core interaction -> split R[B,448]
    gather_interact_kernel<<<B_SZ, 128>>>(x, emb, lsi, Rh, Rl);

    // launches 4-5: top MLP (t1 fuses the final 256->1 dot via atomics)
    gemm_mma<<<dim3(8, 128), 256, SMEM>>>(Rh, Rl, tW0h, tW0l, tb0, 448, 7,
                                          nullptr, z1h, z1l, 512, 1, 1,
                                          nullptr, nullptr);
    gemm_mma<<<dim3(4, 128), 256, SMEM>>>(z1h, z1l, tW1h, tW1l, tb1, 512, 8,
                                          nullptr, nullptr, nullptr, 256, 1, 0,
                                          tW2, dot);

    // launch 6: sigmoid
    sigmoid_kernel<<<B_SZ / 256, 256>>>(dot, tb2, (float*)d_out);
}